// round 2
// baseline (speedup 1.0000x reference)
#include <cuda_runtime.h>
#include <math.h>

#define TWO_PI 6.283185307179586f

// ---- static device scratch (allocation-free) ----
// A: FFT intermediate, reused across volumes (launches are stream-ordered)
__device__ float2 g_A [128 * 256 * 256];          // 67 MB
// Channel-last volumes: V[u][v][c], c contiguous (128 complex per (u,v))
__device__ float2 g_Vx[256 * 256 * 128];          // 67 MB
__device__ float2 g_Vy[256 * 256 * 128];
__device__ float2 g_Vz[256 * 256 * 128];

// ----------------------------------------------------------------------------
// 256-point inverse DFT (e^{+i}, unnormalized) on 16 lines in shared memory.
// Radix 16x16: X[16n1+n0] = sum_k0 cis16[k0*n1] * ( W256[k0*n0] *
//                            sum_k1 x[16k1+k0] * cis16[k1*n0] )
// 16 threads per line (thread id within line = k0 for stage 1, n0 for stage 2).
// ----------------------------------------------------------------------------
__device__ __forceinline__ void fft256_16lines(float2 (*sh)[272],
                                               const float2* cis16,
                                               const float2* w256,
                                               int line, int k0) {
    float2 x[16];
#pragma unroll
    for (int k1 = 0; k1 < 16; ++k1) x[k1] = sh[line][k1 * 16 + k0];
    __syncthreads();
#pragma unroll
    for (int n0 = 0; n0 < 16; ++n0) {
        float2 acc = make_float2(0.f, 0.f);
#pragma unroll
        for (int k1 = 0; k1 < 16; ++k1) {
            float2 w = cis16[(k1 * n0) & 15];
            acc.x = fmaf(x[k1].x, w.x, fmaf(-x[k1].y, w.y, acc.x));
            acc.y = fmaf(x[k1].x, w.y, fmaf( x[k1].y, w.x, acc.y));
        }
        float2 tw = w256[k0 * 16 + n0];
        sh[line][k0 * 17 + n0] = make_float2(acc.x * tw.x - acc.y * tw.y,
                                             acc.x * tw.y + acc.y * tw.x);
    }
    __syncthreads();
    const int n0 = k0;
    float2 y[16];
#pragma unroll
    for (int kk = 0; kk < 16; ++kk) y[kk] = sh[line][kk * 17 + n0];
    __syncthreads();
#pragma unroll
    for (int n1 = 0; n1 < 16; ++n1) {
        float2 acc = make_float2(0.f, 0.f);
#pragma unroll
        for (int kk = 0; kk < 16; ++kk) {
            float2 w = cis16[(kk * n1) & 15];
            acc.x = fmaf(y[kk].x, w.x, fmaf(-y[kk].y, w.y, acc.x));
            acc.y = fmaf(y[kk].x, w.y, fmaf( y[kk].y, w.x, acc.y));
        }
        sh[line][n1 * 16 + n0] = acc;   // natural order X[16n1+n0]
    }
    __syncthreads();
}

__device__ __forceinline__ void init_tables(float2* cis16, float2* w256, int t) {
    int k0 = t >> 4, n0 = t & 15;
    float s, c;
    sincosf(TWO_PI * (float)(k0 * n0) * (1.f / 256.f), &s, &c);
    w256[t] = make_float2(c, s);
    if (t < 16) {
        float s2, c2;
        sincosf(TWO_PI * (float)t * (1.f / 16.f), &s2, &c2);
        cis16[t] = make_float2(c2, s2);
    }
}

// ----------------------------------------------------------------------------
// Pass 1: inverse DFT along the contiguous-ish transform axis (v).
// Writes A[c][u][v] (standard layout, line-contiguous).
// MODE 0: Fx [c=f*8+d][y=u][z=v], v contiguous.
// MODE 1: Fy [f][x=u][d][z=v],    v contiguous (per (f,x,d) line).
// MODE 2: Fz [f][x=u][y=v][d],    v stride 8; lines grouped (f,x,d) d-fastest
//         so a block covers 2 contiguous 8KB input chunks.
// ----------------------------------------------------------------------------
template <int MODE>
__global__ __launch_bounds__(256) void k_fft_pass1(const float* __restrict__ re,
                                                   const float* __restrict__ im,
                                                   const float* __restrict__ alphap) {
    __shared__ float2 sh[16][272];
    __shared__ float2 w256[256];
    __shared__ float2 cis16[16];
    const int t = threadIdx.x;
    init_tables(cis16, w256, t);

    const float ap = alphap[0];
    const float bx = 10.f * ap;
    const float alpha = (bx > 1.f) ? ap : 0.1f * log1pf(expf(fminf(bx, 30.f)));

    const int line0 = blockIdx.x * 16;

    if (MODE == 2) {
        const int f = line0 >> 11, x0 = (line0 >> 3) & 255;
        const int base = f * 524288 + x0 * 2048;
#pragma unroll
        for (int j = 0; j < 16; ++j) {
            int e = t + 256 * j;                 // linear within 2x8KB chunk
            int d = e & 7, v = (e >> 3) & 255, xo = e >> 11;
            sh[xo * 8 + d][v] = make_float2(re[base + e] * alpha,
                                            im[base + e] * alpha);
        }
    } else {
#pragma unroll
        for (int j = 0; j < 16; ++j) {
            int e = t + 256 * j;
            int li = e >> 8, v = e & 255;
            int L = line0 + li;
            int idx;
            if (MODE == 0) {
                idx = L * 256 + v;
            } else {
                int c = L >> 8, xx = L & 255, f = c >> 3, d = c & 7;
                idx = f * 524288 + xx * 2048 + d * 256 + v;
            }
            sh[li][v] = make_float2(re[idx] * alpha, im[idx] * alpha);
        }
    }
    __syncthreads();
    fft256_16lines(sh, cis16, w256, t >> 4, t & 15);

#pragma unroll
    for (int j = 0; j < 16; ++j) {
        int e = t + 256 * j;
        int li = e >> 8, v = e & 255;
        int L = line0 + li;
        int oidx;
        if (MODE == 2) {
            int f = L >> 11, xx = (L >> 3) & 255, d = L & 7;
            int c = f * 8 + d;
            oidx = (c * 256 + xx) * 256 + v;
        } else {
            oidx = L * 256 + v;
        }
        g_A[oidx] = sh[li][v];
    }
}

// ----------------------------------------------------------------------------
// Pass 2: inverse DFT along u (stride axis of A), output channel-last V[u][v][c].
// Block = 16 channels (c0..c0+15) at one v. blockIdx: v fastest for L2 reuse.
// Stores: 16 consecutive channels -> 128B coalesced chunks.
// ----------------------------------------------------------------------------
template <int VOL>
__global__ __launch_bounds__(256) void k_fft_pass2() {
    __shared__ float2 sh[16][272];
    __shared__ float2 w256[256];
    __shared__ float2 cis16[16];
    const int t = threadIdx.x;
    init_tables(cis16, w256, t);

    float2* __restrict__ V = (VOL == 0) ? g_Vx : (VOL == 1) ? g_Vy : g_Vz;

    const int b = blockIdx.x;
    const int v = b & 255;
    const int c0 = (b >> 8) * 16;

#pragma unroll
    for (int j = 0; j < 16; ++j) {
        sh[j][t] = g_A[((c0 + j) * 256 + t) * 256 + v];
    }
    __syncthreads();
    fft256_16lines(sh, cis16, w256, t >> 4, t & 15);

#pragma unroll
    for (int j = 0; j < 16; ++j) {
        int e = t + 256 * j;
        int cl = e & 15, u = e >> 4;
        V[(u * 256 + v) * 128 + c0 + cl] = sh[cl][u];
    }
}

// ----------------------------------------------------------------------------
// Sampling: one warp per point, lane handles channels [4*lane, 4*lane+4).
// Bilinear taps are 1KB-contiguous warp reads. Twiddle reduce + shfl combine.
// ----------------------------------------------------------------------------
__device__ __forceinline__ float plane_eval(const float2* __restrict__ V,
                                            float gu, float gv, float tx,
                                            int cbase) {
    float iu = (gu + 1.f) * 127.5f;          // (g+1)*0.5*(256-1)
    float iv = (gv + 1.f) * 127.5f;
    float u0f = floorf(iu), v0f = floorf(iv);
    float wu = iu - u0f, wv = iv - v0f;
    int u0 = (int)u0f; u0 = max(0, min(u0, 255)); int u1 = min(u0 + 1, 255);
    int v0 = (int)v0f; v0 = max(0, min(v0, 255)); int v1 = min(v0 + 1, 255);

    const float4* p00 = (const float4*)(V + ((u0 * 256 + v0) * 128 + cbase));
    const float4* p01 = (const float4*)(V + ((u0 * 256 + v1) * 128 + cbase));
    const float4* p10 = (const float4*)(V + ((u1 * 256 + v0) * 128 + cbase));
    const float4* p11 = (const float4*)(V + ((u1 * 256 + v1) * 128 + cbase));
    float4 a00 = p00[0], b00 = p00[1];
    float4 a01 = p01[0], b01 = p01[1];
    float4 a10 = p10[0], b10 = p10[1];
    float4 a11 = p11[0], b11 = p11[1];

    float w00 = (1.f - wu) * (1.f - wv), w01 = (1.f - wu) * wv;
    float w10 = wu * (1.f - wv),         w11 = wu * wv;

    float sr[4], si[4];
    sr[0] = w00*a00.x + w01*a01.x + w10*a10.x + w11*a11.x;
    si[0] = w00*a00.y + w01*a01.y + w10*a10.y + w11*a11.y;
    sr[1] = w00*a00.z + w01*a01.z + w10*a10.z + w11*a11.z;
    si[1] = w00*a00.w + w01*a01.w + w10*a10.w + w11*a11.w;
    sr[2] = w00*b00.x + w01*b01.x + w10*b10.x + w11*b11.x;
    si[2] = w00*b00.y + w01*b01.y + w10*b10.y + w11*b11.y;
    sr[3] = w00*b00.z + w01*b01.z + w10*b10.z + w11*b11.z;
    si[3] = w00*b00.w + w01*b01.w + w10*b10.w + w11*b11.w;

    float xx = (tx + 1.f) * 0.5f * (255.f / 256.f);
    float bang = TWO_PI * xx;
    int d0 = cbase & 7;
    float res = 0.f;
#pragma unroll
    for (int j = 0; j < 4; ++j) {
        int d = d0 + j;
        float sn, cn;
        __sincosf(bang * (float)d, &sn, &cn);
        float sc = (d > 0) ? 2.f : 1.f;
        res += sc * (sr[j] * cn - si[j] * sn);
    }
    return res;
}

__global__ __launch_bounds__(256) void k_sample(const float* __restrict__ pts,
                                                float* __restrict__ out) {
    int gw = (blockIdx.x * 256 + threadIdx.x) >> 5;
    int lane = threadIdx.x & 31;
    if (gw >= 131072) return;
    float xs = pts[gw * 3 + 0];
    float ys = pts[gw * 3 + 1];
    float zs = pts[gw * 3 + 2];
    int cbase = lane * 4;

    // plane X: sample (H=ys, W=zs), twiddle with xs
    // plane Y: sample (H=xs, W=zs), twiddle with ys
    // plane Z: V_z[x][y], sample (u=xs, v=ys), twiddle with zs
    float acc = plane_eval(g_Vx, ys, zs, xs, cbase)
              + plane_eval(g_Vy, xs, zs, ys, cbase)
              + plane_eval(g_Vz, xs, ys, zs, cbase);

    // lane pair (2f, 2f+1) holds feature f = lane>>1
    acc += __shfl_xor_sync(0xffffffffu, acc, 1);
    float vv = __shfl_sync(0xffffffffu, acc, (lane & 15) * 2);
    if (lane < 16) out[gw * 16 + lane] = vv;
}

extern "C" void kernel_launch(void* const* d_in, const int* in_sizes, int n_in,
                              void* d_out, int out_size) {
    const float* pts    = (const float*)d_in[0];
    const float* Fx_re  = (const float*)d_in[1];
    const float* Fx_im  = (const float*)d_in[2];
    const float* Fy_re  = (const float*)d_in[3];
    const float* Fy_im  = (const float*)d_in[4];
    const float* Fz_re  = (const float*)d_in[5];
    const float* Fz_im  = (const float*)d_in[6];
    const float* alphap = (const float*)d_in[7];
    float* out = (float*)d_out;

    k_fft_pass1<0><<<2048, 256>>>(Fx_re, Fx_im, alphap);
    k_fft_pass2<0><<<2048, 256>>>();
    k_fft_pass1<1><<<2048, 256>>>(Fy_re, Fy_im, alphap);
    k_fft_pass2<1><<<2048, 256>>>();
    k_fft_pass1<2><<<2048, 256>>>(Fz_re, Fz_im, alphap);
    k_fft_pass2<2><<<2048, 256>>>();
    k_sample<<<131072 * 32 / 256, 256>>>(pts, out);
}

// round 3
// speedup vs baseline: 1.8000x; 1.8000x over previous
#include <cuda_runtime.h>
#include <cuda_fp16.h>
#include <math.h>

#define TWO_PI 6.283185307179586f

// ---- static device scratch (allocation-free) ----
__device__ float2 g_A [128 * 256 * 256];                 // 67 MB fp32 intermediate
__device__ __align__(16) __half2 g_Vx[256 * 256 * 128];  // 33.5 MB channel-last
__device__ __align__(16) __half2 g_Vy[256 * 256 * 128];
__device__ __align__(16) __half2 g_Vz[256 * 256 * 128];

// ---------------------------------------------------------------------------
// complex helpers
// ---------------------------------------------------------------------------
__device__ __forceinline__ float2 cmul(float2 a, float2 b) {
    return make_float2(fmaf(a.x, b.x, -a.y * b.y), fmaf(a.x, b.y, a.y * b.x));
}
__device__ __forceinline__ float2 cmul_imm(float2 a, float c, float s) {
    // a * (c + i s) with c,s immediates
    return make_float2(fmaf(a.x, c, a.y * (-s)), fmaf(a.y, c, a.x * s));
}
__device__ __forceinline__ float2 cadd(float2 a, float2 b) { return make_float2(a.x + b.x, a.y + b.y); }
__device__ __forceinline__ float2 csub(float2 a, float2 b) { return make_float2(a.x - b.x, a.y - b.y); }
__device__ __forceinline__ float2 muli(float2 a) { return make_float2(-a.y, a.x); }  // * (+i)

// inverse DFT4 (W4 = +i)
__device__ __forceinline__ void dft4(float2 x0, float2 x1, float2 x2, float2 x3,
                                     float2& X0, float2& X1, float2& X2, float2& X3) {
    float2 t0 = cadd(x0, x2), t1 = csub(x0, x2);
    float2 t2 = cadd(x1, x3), t3 = csub(x1, x3);
    X0 = cadd(t0, t2);
    X2 = csub(t0, t2);
    float2 it3 = muli(t3);
    X1 = cadd(t1, it3);
    X3 = csub(t1, it3);
}

// inverse 16-point DFT, radix-4x4, natural-order in/out.
// X[n] = sum_k x[k] e^{+2pi i k n / 16}
__device__ __forceinline__ void ifft16(const float2 x[16], float2 X[16]) {
    const float C  = 0.70710678118654752f;
    const float c1 = 0.92387953251128676f;
    const float s1 = 0.38268343236508977f;
    float2 y[16];  // y[4*k1 + n2]
#pragma unroll
    for (int k1 = 0; k1 < 4; ++k1)
        dft4(x[k1], x[k1 + 4], x[k1 + 8], x[k1 + 12],
             y[4 * k1 + 0], y[4 * k1 + 1], y[4 * k1 + 2], y[4 * k1 + 3]);
    // twiddle y[k1][n2] *= W16^{k1*n2}
    y[4 * 1 + 1] = cmul_imm(y[4 * 1 + 1],  c1,  s1);   // W^1
    y[4 * 1 + 2] = cmul_imm(y[4 * 1 + 2],   C,   C);   // W^2
    y[4 * 1 + 3] = cmul_imm(y[4 * 1 + 3],  s1,  c1);   // W^3
    y[4 * 2 + 1] = cmul_imm(y[4 * 2 + 1],   C,   C);   // W^2
    y[4 * 2 + 2] = muli(y[4 * 2 + 2]);                 // W^4 = i
    y[4 * 2 + 3] = cmul_imm(y[4 * 2 + 3],  -C,   C);   // W^6
    y[4 * 3 + 1] = cmul_imm(y[4 * 3 + 1],  s1,  c1);   // W^3
    y[4 * 3 + 2] = cmul_imm(y[4 * 3 + 2],  -C,   C);   // W^6
    y[4 * 3 + 3] = cmul_imm(y[4 * 3 + 3], -c1, -s1);   // W^9
#pragma unroll
    for (int n2 = 0; n2 < 4; ++n2) {
        float2 z0, z1, z2, z3;
        dft4(y[4 * 0 + n2], y[4 * 1 + n2], y[4 * 2 + n2], y[4 * 3 + n2], z0, z1, z2, z3);
        X[n2] = z0; X[4 + n2] = z1; X[8 + n2] = z2; X[12 + n2] = z3;
    }
}

// ----------------------------------------------------------------------------
// 256-point inverse DFT (e^{+i}, unnormalized) on 16 lines in shared memory.
// X[16 n1 + n0] = IFFT16_{k0->n1}( W256^{k0 n0} * IFFT16_{k1->n0}(x[16k1+k0]) )
// thread role: line = t>>4, k0(stage1)/n0(stage2) = t&15. No smem tables.
// ----------------------------------------------------------------------------
__device__ __forceinline__ void fft256_16lines(float2 (*sh)[272], int line, int k0) {
    float2 x[16];
#pragma unroll
    for (int k1 = 0; k1 < 16; ++k1) x[k1] = sh[line][k1 * 16 + k0];
    __syncthreads();
    float2 X[16];
    ifft16(x, X);
    float sb, cb;
    sincosf((float)k0 * (TWO_PI / 256.f), &sb, &cb);
    float2 base = make_float2(cb, sb);
    float2 tw = make_float2(1.f, 0.f);
#pragma unroll
    for (int n0 = 0; n0 < 16; ++n0) {
        sh[line][k0 * 17 + n0] = cmul(X[n0], tw);
        tw = cmul(tw, base);
    }
    __syncthreads();
    const int n0 = k0;
    float2 y[16];
#pragma unroll
    for (int kk = 0; kk < 16; ++kk) y[kk] = sh[line][kk * 17 + n0];
    __syncthreads();
    float2 Y[16];
    ifft16(y, Y);
#pragma unroll
    for (int n1 = 0; n1 < 16; ++n1) sh[line][n1 * 16 + n0] = Y[n1];
    __syncthreads();
}

// ----------------------------------------------------------------------------
// Pass 1: inverse DFT along contiguous axis v. Writes A[c][u][v].
// MODE 0: Fx [c][y=u][z=v]; MODE 1: Fy [f][x=u][d][z=v]; MODE 2: Fz [f][x=u][y=v][d]
// ----------------------------------------------------------------------------
template <int MODE>
__global__ __launch_bounds__(256) void k_fft_pass1(const float* __restrict__ re,
                                                   const float* __restrict__ im,
                                                   const float* __restrict__ alphap) {
    __shared__ float2 sh[16][272];
    const int t = threadIdx.x;

    const float ap = alphap[0];
    const float bx = 10.f * ap;
    const float alpha = (bx > 1.f) ? ap : 0.1f * log1pf(expf(fminf(bx, 30.f)));

    const int line0 = blockIdx.x * 16;

    if (MODE == 2) {
        const int f = line0 >> 11, x0 = (line0 >> 3) & 255;
        const int base = f * 524288 + x0 * 2048;
#pragma unroll
        for (int j = 0; j < 16; ++j) {
            int e = t + 256 * j;
            int d = e & 7, v = (e >> 3) & 255, xo = e >> 11;
            sh[xo * 8 + d][v] = make_float2(re[base + e] * alpha,
                                            im[base + e] * alpha);
        }
    } else {
#pragma unroll
        for (int j = 0; j < 16; ++j) {
            int e = t + 256 * j;
            int li = e >> 8, v = e & 255;
            int L = line0 + li;
            int idx;
            if (MODE == 0) {
                idx = L * 256 + v;
            } else {
                int c = L >> 8, xx = L & 255, f = c >> 3, d = c & 7;
                idx = f * 524288 + xx * 2048 + d * 256 + v;
            }
            sh[li][v] = make_float2(re[idx] * alpha, im[idx] * alpha);
        }
    }
    __syncthreads();
    fft256_16lines(sh, t >> 4, t & 15);

#pragma unroll
    for (int j = 0; j < 16; ++j) {
        int e = t + 256 * j;
        int li = e >> 8, v = e & 255;
        int L = line0 + li;
        int oidx;
        if (MODE == 2) {
            int f = L >> 11, xx = (L >> 3) & 255, d = L & 7;
            int c = f * 8 + d;
            oidx = (c * 256 + xx) * 256 + v;
        } else {
            oidx = L * 256 + v;
        }
        g_A[oidx] = sh[li][v];
    }
}

// ----------------------------------------------------------------------------
// Pass 2: inverse DFT along u; output channel-last fp16 V[u][v][c].
// ----------------------------------------------------------------------------
template <int VOL>
__global__ __launch_bounds__(256) void k_fft_pass2() {
    __shared__ float2 sh[16][272];
    const int t = threadIdx.x;

    __half2* __restrict__ V = (VOL == 0) ? g_Vx : (VOL == 1) ? g_Vy : g_Vz;

    const int b = blockIdx.x;
    const int v = b & 255;
    const int c0 = (b >> 8) * 16;

#pragma unroll
    for (int j = 0; j < 16; ++j) {
        sh[j][t] = g_A[((c0 + j) * 256 + t) * 256 + v];
    }
    __syncthreads();
    fft256_16lines(sh, t >> 4, t & 15);

#pragma unroll
    for (int j = 0; j < 16; ++j) {
        int e = t + 256 * j;
        int cl = e & 15, u = e >> 4;
        float2 val = sh[cl][u];
        V[(u * 256 + v) * 128 + c0 + cl] = __floats2half2_rn(val.x, val.y);
    }
}

// ----------------------------------------------------------------------------
// Sampling: one warp per point, lane = 4 channels. 16B vector taps from fp16.
// ----------------------------------------------------------------------------
__device__ __forceinline__ void load4h(const __half2* __restrict__ V, int off, float2 r[4]) {
    uint4 q = *reinterpret_cast<const uint4*>(V + off);
    r[0] = __half22float2(*reinterpret_cast<__half2*>(&q.x));
    r[1] = __half22float2(*reinterpret_cast<__half2*>(&q.y));
    r[2] = __half22float2(*reinterpret_cast<__half2*>(&q.z));
    r[3] = __half22float2(*reinterpret_cast<__half2*>(&q.w));
}

__device__ __forceinline__ float plane_eval(const __half2* __restrict__ V,
                                            float gu, float gv, float tx,
                                            int cbase) {
    float iu = (gu + 1.f) * 127.5f;
    float iv = (gv + 1.f) * 127.5f;
    float u0f = floorf(iu), v0f = floorf(iv);
    float wu = iu - u0f, wv = iv - v0f;
    int u0 = (int)u0f; u0 = max(0, min(u0, 255)); int u1 = min(u0 + 1, 255);
    int v0 = (int)v0f; v0 = max(0, min(v0, 255)); int v1 = min(v0 + 1, 255);

    float2 t00[4], t01[4], t10[4], t11[4];
    load4h(V, (u0 * 256 + v0) * 128 + cbase, t00);
    load4h(V, (u0 * 256 + v1) * 128 + cbase, t01);
    load4h(V, (u1 * 256 + v0) * 128 + cbase, t10);
    load4h(V, (u1 * 256 + v1) * 128 + cbase, t11);

    float w00 = (1.f - wu) * (1.f - wv), w01 = (1.f - wu) * wv;
    float w10 = wu * (1.f - wv),         w11 = wu * wv;

    float xx = (tx + 1.f) * 0.5f * (255.f / 256.f);
    float bang = TWO_PI * xx;
    int d0 = cbase & 7;
    float res = 0.f;
#pragma unroll
    for (int j = 0; j < 4; ++j) {
        float sr = w00 * t00[j].x + w01 * t01[j].x + w10 * t10[j].x + w11 * t11[j].x;
        float si = w00 * t00[j].y + w01 * t01[j].y + w10 * t10[j].y + w11 * t11[j].y;
        int d = d0 + j;
        float sn, cn;
        __sincosf(bang * (float)d, &sn, &cn);
        float sc = (d > 0) ? 2.f : 1.f;
        res += sc * (sr * cn - si * sn);
    }
    return res;
}

__global__ __launch_bounds__(256) void k_sample(const float* __restrict__ pts,
                                                float* __restrict__ out) {
    int gw = (blockIdx.x * 256 + threadIdx.x) >> 5;
    int lane = threadIdx.x & 31;
    if (gw >= 131072) return;
    float xs = pts[gw * 3 + 0];
    float ys = pts[gw * 3 + 1];
    float zs = pts[gw * 3 + 2];
    int cbase = lane * 4;

    float acc = plane_eval(g_Vx, ys, zs, xs, cbase)
              + plane_eval(g_Vy, xs, zs, ys, cbase)
              + plane_eval(g_Vz, xs, ys, zs, cbase);

    acc += __shfl_xor_sync(0xffffffffu, acc, 1);
    float vv = __shfl_sync(0xffffffffu, acc, (lane & 15) * 2);
    if (lane < 16) out[gw * 16 + lane] = vv;
}

extern "C" void kernel_launch(void* const* d_in, const int* in_sizes, int n_in,
                              void* d_out, int out_size) {
    const float* pts    = (const float*)d_in[0];
    const float* Fx_re  = (const float*)d_in[1];
    const float* Fx_im  = (const float*)d_in[2];
    const float* Fy_re  = (const float*)d_in[3];
    const float* Fy_im  = (const float*)d_in[4];
    const float* Fz_re  = (const float*)d_in[5];
    const float* Fz_im  = (const float*)d_in[6];
    const float* alphap = (const float*)d_in[7];
    float* out = (float*)d_out;

    k_fft_pass1<0><<<2048, 256>>>(Fx_re, Fx_im, alphap);
    k_fft_pass2<0><<<2048, 256>>>();
    k_fft_pass1<1><<<2048, 256>>>(Fy_re, Fy_im, alphap);
    k_fft_pass2<1><<<2048, 256>>>();
    k_fft_pass1<2><<<2048, 256>>>(Fz_re, Fz_im, alphap);
    k_fft_pass2<2><<<2048, 256>>>();
    k_sample<<<131072 * 32 / 256, 256>>>(pts, out);
}

// round 5
// speedup vs baseline: 3.1328x; 1.7404x over previous
#include <cuda_runtime.h>
#include <cuda_fp16.h>
#include <math.h>

#define TWO_PI 6.283185307179586f

// ---- static device scratch (allocation-free) ----
// A: FFT intermediate, channel-last: A[u][v][c], c contiguous (128 float2)
__device__ __align__(16) float2 g_A [256 * 256 * 128];   // 67 MB
// Sampled volumes, channel-last fp16: V[u][v][c]
__device__ __align__(16) __half2 g_Vx[256 * 256 * 128];  // 33.5 MB
__device__ __align__(16) __half2 g_Vy[256 * 256 * 128];
__device__ __align__(16) __half2 g_Vz[256 * 256 * 128];

#define SH_R 273   // smem row stride (float2 units); 2*273 mod 32 = 2 -> low conflicts

// ---------------------------------------------------------------------------
// complex helpers
// ---------------------------------------------------------------------------
__device__ __forceinline__ float2 cmul(float2 a, float2 b) {
    return make_float2(fmaf(a.x, b.x, -a.y * b.y), fmaf(a.x, b.y, a.y * b.x));
}
__device__ __forceinline__ float2 cmul_imm(float2 a, float c, float s) {
    return make_float2(fmaf(a.x, c, a.y * (-s)), fmaf(a.y, c, a.x * s));
}
__device__ __forceinline__ float2 cadd(float2 a, float2 b) { return make_float2(a.x + b.x, a.y + b.y); }
__device__ __forceinline__ float2 csub(float2 a, float2 b) { return make_float2(a.x - b.x, a.y - b.y); }
__device__ __forceinline__ float2 muli(float2 a) { return make_float2(-a.y, a.x); }  // * (+i)

// inverse DFT4 (W4 = +i)
__device__ __forceinline__ void dft4(float2 x0, float2 x1, float2 x2, float2 x3,
                                     float2& X0, float2& X1, float2& X2, float2& X3) {
    float2 t0 = cadd(x0, x2), t1 = csub(x0, x2);
    float2 t2 = cadd(x1, x3), t3 = csub(x1, x3);
    X0 = cadd(t0, t2);
    X2 = csub(t0, t2);
    float2 it3 = muli(t3);
    X1 = cadd(t1, it3);
    X3 = csub(t1, it3);
}

// inverse 16-point DFT, radix-4x4, natural-order in/out.
__device__ __forceinline__ void ifft16(const float2 x[16], float2 X[16]) {
    const float C  = 0.70710678118654752f;
    const float c1 = 0.92387953251128676f;
    const float s1 = 0.38268343236508977f;
    float2 y[16];
#pragma unroll
    for (int k1 = 0; k1 < 4; ++k1)
        dft4(x[k1], x[k1 + 4], x[k1 + 8], x[k1 + 12],
             y[4 * k1 + 0], y[4 * k1 + 1], y[4 * k1 + 2], y[4 * k1 + 3]);
    y[4 * 1 + 1] = cmul_imm(y[4 * 1 + 1],  c1,  s1);
    y[4 * 1 + 2] = cmul_imm(y[4 * 1 + 2],   C,   C);
    y[4 * 1 + 3] = cmul_imm(y[4 * 1 + 3],  s1,  c1);
    y[4 * 2 + 1] = cmul_imm(y[4 * 2 + 1],   C,   C);
    y[4 * 2 + 2] = muli(y[4 * 2 + 2]);
    y[4 * 2 + 3] = cmul_imm(y[4 * 2 + 3],  -C,   C);
    y[4 * 3 + 1] = cmul_imm(y[4 * 3 + 1],  s1,  c1);
    y[4 * 3 + 2] = cmul_imm(y[4 * 3 + 2],  -C,   C);
    y[4 * 3 + 3] = cmul_imm(y[4 * 3 + 3], -c1, -s1);
#pragma unroll
    for (int n2 = 0; n2 < 4; ++n2) {
        float2 z0, z1, z2, z3;
        dft4(y[4 * 0 + n2], y[4 * 1 + n2], y[4 * 2 + n2], y[4 * 3 + n2], z0, z1, z2, z3);
        X[n2] = z0; X[4 + n2] = z1; X[8 + n2] = z2; X[12 + n2] = z3;
    }
}

// ----------------------------------------------------------------------------
// 256-point inverse DFT (e^{+i}, unnormalized) on 16 lines in shared memory.
// ----------------------------------------------------------------------------
__device__ __forceinline__ void fft256_16lines(float2 (*sh)[SH_R], int line, int k0) {
    float2 x[16];
#pragma unroll
    for (int k1 = 0; k1 < 16; ++k1) x[k1] = sh[line][k1 * 16 + k0];
    __syncthreads();
    float2 X[16];
    ifft16(x, X);
    float sb, cb;
    sincosf((float)k0 * (TWO_PI / 256.f), &sb, &cb);
    float2 base = make_float2(cb, sb);
    float2 tw = make_float2(1.f, 0.f);
#pragma unroll
    for (int n0 = 0; n0 < 16; ++n0) {
        sh[line][k0 * 17 + n0] = cmul(X[n0], tw);
        tw = cmul(tw, base);
    }
    __syncthreads();
    const int n0 = k0;
    float2 y[16];
#pragma unroll
    for (int kk = 0; kk < 16; ++kk) y[kk] = sh[line][kk * 17 + n0];
    __syncthreads();
    float2 Y[16];
    ifft16(y, Y);
#pragma unroll
    for (int n1 = 0; n1 < 16; ++n1) sh[line][n1 * 16 + n0] = Y[n1];
    __syncthreads();
}

// ----------------------------------------------------------------------------
// Pass 1: inverse DFT along contiguous axis v.
// Block = 16 consecutive channels at ONE u:  b -> u = b&255, c0 = (b>>8)*16.
// Writes channel-last A[u][v][c] (128B-coalesced per 16 lanes).
// MODE 0: Fx [c][y=u][z=v]; MODE 1: Fy [f][x=u][d][z=v]; MODE 2: Fz [f][x=u][y=v][d]
// ----------------------------------------------------------------------------
template <int MODE>
__global__ __launch_bounds__(256) void k_fft_pass1(const float* __restrict__ re,
                                                   const float* __restrict__ im,
                                                   const float* __restrict__ alphap) {
    __shared__ float2 sh[16][SH_R];
    const int t = threadIdx.x;

    const float ap = alphap[0];
    const float bxx = 10.f * ap;
    const float alpha = (bxx > 1.f) ? ap : 0.1f * log1pf(expf(fminf(bxx, 30.f)));

    const int b = blockIdx.x;
    const int u = b & 255;
    const int c0 = (b >> 8) * 16;

    if (MODE == 2) {
        // 16 channels = 2 f x 8 d; two contiguous 8KB input chunks
        const int f0 = c0 >> 3;
        const int base = f0 * 524288 + u * 2048;
#pragma unroll
        for (int j = 0; j < 16; ++j) {
            int e = t + 256 * j;                  // 0..4095
            int f_loc = e >> 11, r = e & 2047;
            int d = r & 7, v = r >> 3;
            sh[f_loc * 8 + d][v] = make_float2(re[base + f_loc * 524288 + r] * alpha,
                                               im[base + f_loc * 524288 + r] * alpha);
        }
    } else {
#pragma unroll
        for (int j = 0; j < 16; ++j) {
            int e = t + 256 * j;
            int li = e >> 8, v = e & 255;
            int c = c0 + li;
            int idx;
            if (MODE == 0) {
                idx = c * 65536 + u * 256 + v;
            } else {
                int f = c >> 3, d = c & 7;
                idx = f * 524288 + u * 2048 + d * 256 + v;
            }
            sh[li][v] = make_float2(re[idx] * alpha, im[idx] * alpha);
        }
    }
    __syncthreads();
    fft256_16lines(sh, t >> 4, t & 15);

    // store channel-last: lanes 0..15 -> 16 consecutive channels = 128B
#pragma unroll
    for (int j = 0; j < 16; ++j) {
        int e = t + 256 * j;
        int cl = e & 15, v = e >> 4;
        g_A[(u * 256 + v) * 128 + c0 + cl] = sh[cl][v];
    }
}

// ----------------------------------------------------------------------------
// Pass 2: inverse DFT along u. Block = 16 channels at ONE v.
// Loads A[u][v][c] 128B-coalesced; stores fp16 V[u][v][c] 64B-coalesced.
// ----------------------------------------------------------------------------
template <int VOL>
__global__ __launch_bounds__(256) void k_fft_pass2() {
    __shared__ float2 sh[16][SH_R];
    const int t = threadIdx.x;

    __half2* __restrict__ V = (VOL == 0) ? g_Vx : (VOL == 1) ? g_Vy : g_Vz;

    const int b = blockIdx.x;
    const int v = b & 255;
    const int c0 = (b >> 8) * 16;

#pragma unroll
    for (int j = 0; j < 16; ++j) {
        int e = t + 256 * j;
        int cl = e & 15, u = e >> 4;
        sh[cl][u] = g_A[(u * 256 + v) * 128 + c0 + cl];
    }
    __syncthreads();
    fft256_16lines(sh, t >> 4, t & 15);

#pragma unroll
    for (int j = 0; j < 16; ++j) {
        int e = t + 256 * j;
        int cl = e & 15, u = e >> 4;
        float2 val = sh[cl][u];
        V[(u * 256 + v) * 128 + c0 + cl] = __floats2half2_rn(val.x, val.y);
    }
}

// ----------------------------------------------------------------------------
// Sampling: one warp per point, lane = 4 channels. 16B vector taps from fp16.
// ----------------------------------------------------------------------------
__device__ __forceinline__ void load4h(const __half2* __restrict__ V, int off, float2 r[4]) {
    uint4 q = *reinterpret_cast<const uint4*>(V + off);
    r[0] = __half22float2(*reinterpret_cast<__half2*>(&q.x));
    r[1] = __half22float2(*reinterpret_cast<__half2*>(&q.y));
    r[2] = __half22float2(*reinterpret_cast<__half2*>(&q.z));
    r[3] = __half22float2(*reinterpret_cast<__half2*>(&q.w));
}

__device__ __forceinline__ float plane_eval(const __half2* __restrict__ V,
                                            float gu, float gv, float tx,
                                            int cbase) {
    float iu = (gu + 1.f) * 127.5f;
    float iv = (gv + 1.f) * 127.5f;
    float u0f = floorf(iu), v0f = floorf(iv);
    float wu = iu - u0f, wv = iv - v0f;
    int u0 = (int)u0f; u0 = max(0, min(u0, 255)); int u1 = min(u0 + 1, 255);
    int v0 = (int)v0f; v0 = max(0, min(v0, 255)); int v1 = min(v0 + 1, 255);

    float2 t00[4], t01[4], t10[4], t11[4];
    load4h(V, (u0 * 256 + v0) * 128 + cbase, t00);
    load4h(V, (u0 * 256 + v1) * 128 + cbase, t01);
    load4h(V, (u1 * 256 + v0) * 128 + cbase, t10);
    load4h(V, (u1 * 256 + v1) * 128 + cbase, t11);

    float w00 = (1.f - wu) * (1.f - wv), w01 = (1.f - wu) * wv;
    float w10 = wu * (1.f - wv),         w11 = wu * wv;

    float xx = (tx + 1.f) * 0.5f * (255.f / 256.f);
    float bang = TWO_PI * xx;
    int d0 = cbase & 7;
    float res = 0.f;
#pragma unroll
    for (int j = 0; j < 4; ++j) {
        float sr = w00 * t00[j].x + w01 * t01[j].x + w10 * t10[j].x + w11 * t11[j].x;
        float si = w00 * t00[j].y + w01 * t01[j].y + w10 * t10[j].y + w11 * t11[j].y;
        int d = d0 + j;
        float sn, cn;
        __sincosf(bang * (float)d, &sn, &cn);
        float sc = (d > 0) ? 2.f : 1.f;
        res += sc * (sr * cn - si * sn);
    }
    return res;
}

__global__ __launch_bounds__(256) void k_sample(const float* __restrict__ pts,
                                                float* __restrict__ out) {
    int gw = (blockIdx.x * 256 + threadIdx.x) >> 5;
    int lane = threadIdx.x & 31;
    if (gw >= 131072) return;
    float xs = pts[gw * 3 + 0];
    float ys = pts[gw * 3 + 1];
    float zs = pts[gw * 3 + 2];
    int cbase = lane * 4;

    float acc = plane_eval(g_Vx, ys, zs, xs, cbase)
              + plane_eval(g_Vy, xs, zs, ys, cbase)
              + plane_eval(g_Vz, xs, ys, zs, cbase);

    acc += __shfl_xor_sync(0xffffffffu, acc, 1);
    float vv = __shfl_sync(0xffffffffu, acc, (lane & 15) * 2);
    if (lane < 16) out[gw * 16 + lane] = vv;
}

extern "C" void kernel_launch(void* const* d_in, const int* in_sizes, int n_in,
                              void* d_out, int out_size) {
    const float* pts    = (const float*)d_in[0];
    const float* Fx_re  = (const float*)d_in[1];
    const float* Fx_im  = (const float*)d_in[2];
    const float* Fy_re  = (const float*)d_in[3];
    const float* Fy_im  = (const float*)d_in[4];
    const float* Fz_re  = (const float*)d_in[5];
    const float* Fz_im  = (const float*)d_in[6];
    const float* alphap = (const float*)d_in[7];
    float* out = (float*)d_out;

    k_fft_pass1<0><<<2048, 256>>>(Fx_re, Fx_im, alphap);
    k_fft_pass2<0><<<2048, 256>>>();
    k_fft_pass1<1><<<2048, 256>>>(Fy_re, Fy_im, alphap);
    k_fft_pass2<1><<<2048, 256>>>();
    k_fft_pass1<2><<<2048, 256>>>(Fz_re, Fz_im, alphap);
    k_fft_pass2<2><<<2048, 256>>>();
    k_sample<<<131072 * 32 / 256, 256>>>(pts, out);
}

// round 6
// speedup vs baseline: 3.3494x; 1.0691x over previous
#include <cuda_runtime.h>
#include <cuda_fp16.h>
#include <math.h>

#define TWO_PI 6.283185307179586f

// ---- static device scratch (allocation-free) ----
// FFT intermediates (after v-axis transform), channel-last fp16: A[u][v][c]
__device__ __align__(16) __half2 g_A0[256 * 256 * 128];  // 33.5 MB each
__device__ __align__(16) __half2 g_A1[256 * 256 * 128];
__device__ __align__(16) __half2 g_A2[256 * 256 * 128];
// Sampled volumes, channel-last fp16: V[u][v][c]
__device__ __align__(16) __half2 g_Vx[256 * 256 * 128];
__device__ __align__(16) __half2 g_Vy[256 * 256 * 128];
__device__ __align__(16) __half2 g_Vz[256 * 256 * 128];

#define SH_R 273   // smem row stride (float2 units)

// ---------------------------------------------------------------------------
// complex helpers
// ---------------------------------------------------------------------------
__device__ __forceinline__ float2 cmul(float2 a, float2 b) {
    return make_float2(fmaf(a.x, b.x, -a.y * b.y), fmaf(a.x, b.y, a.y * b.x));
}
__device__ __forceinline__ float2 cmul_imm(float2 a, float c, float s) {
    return make_float2(fmaf(a.x, c, a.y * (-s)), fmaf(a.y, c, a.x * s));
}
__device__ __forceinline__ float2 cadd(float2 a, float2 b) { return make_float2(a.x + b.x, a.y + b.y); }
__device__ __forceinline__ float2 csub(float2 a, float2 b) { return make_float2(a.x - b.x, a.y - b.y); }
__device__ __forceinline__ float2 muli(float2 a) { return make_float2(-a.y, a.x); }

__device__ __forceinline__ void dft4(float2 x0, float2 x1, float2 x2, float2 x3,
                                     float2& X0, float2& X1, float2& X2, float2& X3) {
    float2 t0 = cadd(x0, x2), t1 = csub(x0, x2);
    float2 t2 = cadd(x1, x3), t3 = csub(x1, x3);
    X0 = cadd(t0, t2);
    X2 = csub(t0, t2);
    float2 it3 = muli(t3);
    X1 = cadd(t1, it3);
    X3 = csub(t1, it3);
}

// inverse 16-point DFT, radix-4x4, natural-order in/out.
__device__ __forceinline__ void ifft16(const float2 x[16], float2 X[16]) {
    const float C  = 0.70710678118654752f;
    const float c1 = 0.92387953251128676f;
    const float s1 = 0.38268343236508977f;
    float2 y[16];
#pragma unroll
    for (int k1 = 0; k1 < 4; ++k1)
        dft4(x[k1], x[k1 + 4], x[k1 + 8], x[k1 + 12],
             y[4 * k1 + 0], y[4 * k1 + 1], y[4 * k1 + 2], y[4 * k1 + 3]);
    y[4 * 1 + 1] = cmul_imm(y[4 * 1 + 1],  c1,  s1);
    y[4 * 1 + 2] = cmul_imm(y[4 * 1 + 2],   C,   C);
    y[4 * 1 + 3] = cmul_imm(y[4 * 1 + 3],  s1,  c1);
    y[4 * 2 + 1] = cmul_imm(y[4 * 2 + 1],   C,   C);
    y[4 * 2 + 2] = muli(y[4 * 2 + 2]);
    y[4 * 2 + 3] = cmul_imm(y[4 * 2 + 3],  -C,   C);
    y[4 * 3 + 1] = cmul_imm(y[4 * 3 + 1],  s1,  c1);
    y[4 * 3 + 2] = cmul_imm(y[4 * 3 + 2],  -C,   C);
    y[4 * 3 + 3] = cmul_imm(y[4 * 3 + 3], -c1, -s1);
#pragma unroll
    for (int n2 = 0; n2 < 4; ++n2) {
        float2 z0, z1, z2, z3;
        dft4(y[4 * 0 + n2], y[4 * 1 + n2], y[4 * 2 + n2], y[4 * 3 + n2], z0, z1, z2, z3);
        X[n2] = z0; X[4 + n2] = z1; X[8 + n2] = z2; X[12 + n2] = z3;
    }
}

// 256-point inverse DFT on 16 lines in shared memory.
__device__ __forceinline__ void fft256_16lines(float2 (*sh)[SH_R], int line, int k0) {
    float2 x[16];
#pragma unroll
    for (int k1 = 0; k1 < 16; ++k1) x[k1] = sh[line][k1 * 16 + k0];
    __syncthreads();
    float2 X[16];
    ifft16(x, X);
    float sb, cb;
    __sincosf((float)k0 * (TWO_PI / 256.f), &sb, &cb);
    float2 base = make_float2(cb, sb);
    float2 tw = make_float2(1.f, 0.f);
#pragma unroll
    for (int n0 = 0; n0 < 16; ++n0) {
        sh[line][k0 * 17 + n0] = cmul(X[n0], tw);
        tw = cmul(tw, base);
    }
    __syncthreads();
    const int n0 = k0;
    float2 y[16];
#pragma unroll
    for (int kk = 0; kk < 16; ++kk) y[kk] = sh[line][kk * 17 + n0];
    __syncthreads();
    float2 Y[16];
    ifft16(y, Y);
#pragma unroll
    for (int n1 = 0; n1 < 16; ++n1) sh[line][n1 * 16 + n0] = Y[n1];
    __syncthreads();
}

// ----------------------------------------------------------------------------
// Pass 1 (all 3 volumes): inverse DFT along contiguous axis v.
// blockIdx: mode = b>>11; within mode: u = b&255, c0 = ((b>>8)&7)*16.
// Writes channel-last fp16 A[u][v][c].
// MODE 0: Fx [c][y=u][z=v]; MODE 1: Fy [f][x=u][d][z=v]; MODE 2: Fz [f][x=u][y=v][d]
// ----------------------------------------------------------------------------
__global__ __launch_bounds__(256) void k_fft_pass1_all(
        const float* __restrict__ x_re, const float* __restrict__ x_im,
        const float* __restrict__ y_re, const float* __restrict__ y_im,
        const float* __restrict__ z_re, const float* __restrict__ z_im,
        const float* __restrict__ alphap) {
    __shared__ float2 sh[16][SH_R];
    const int t = threadIdx.x;

    const float ap = alphap[0];
    const float bxx = 10.f * ap;
    const float alpha = (bxx > 1.f) ? ap : 0.1f * log1pf(expf(fminf(bxx, 30.f)));

    const int bb = blockIdx.x;
    const int mode = bb >> 11;
    const int b = bb & 2047;
    const int u = b & 255;
    const int c0 = (b >> 8) * 16;

    if (mode == 2) {
        const int f0 = c0 >> 3;
        const int base = f0 * 524288 + u * 2048;
#pragma unroll
        for (int j = 0; j < 16; ++j) {
            int e = t + 256 * j;                  // 0..4095
            int f_loc = e >> 11, r = e & 2047;
            int d = r & 7, v = r >> 3;
            sh[f_loc * 8 + d][v] = make_float2(z_re[base + f_loc * 524288 + r] * alpha,
                                               z_im[base + f_loc * 524288 + r] * alpha);
        }
    } else {
        const float* __restrict__ re = (mode == 0) ? x_re : y_re;
        const float* __restrict__ im = (mode == 0) ? x_im : y_im;
#pragma unroll
        for (int j = 0; j < 16; ++j) {
            int e = t + 256 * j;
            int li = e >> 8, v = e & 255;
            int c = c0 + li;
            int idx;
            if (mode == 0) {
                idx = c * 65536 + u * 256 + v;
            } else {
                int f = c >> 3, d = c & 7;
                idx = f * 524288 + u * 2048 + d * 256 + v;
            }
            sh[li][v] = make_float2(re[idx] * alpha, im[idx] * alpha);
        }
    }
    __syncthreads();
    fft256_16lines(sh, t >> 4, t & 15);

    __half2* __restrict__ A = (mode == 0) ? g_A0 : (mode == 1) ? g_A1 : g_A2;
#pragma unroll
    for (int j = 0; j < 16; ++j) {
        int e = t + 256 * j;
        int cl = e & 15, v = e >> 4;
        float2 val = sh[cl][v];
        A[(u * 256 + v) * 128 + c0 + cl] = __floats2half2_rn(val.x, val.y);
    }
}

// ----------------------------------------------------------------------------
// Pass 2 (all 3 volumes): inverse DFT along u. Block = 16 channels at one v.
// ----------------------------------------------------------------------------
__global__ __launch_bounds__(256) void k_fft_pass2_all() {
    __shared__ float2 sh[16][SH_R];
    const int t = threadIdx.x;

    const int bb = blockIdx.x;
    const int mode = bb >> 11;
    const int b = bb & 2047;
    const int v = b & 255;
    const int c0 = (b >> 8) * 16;

    const __half2* __restrict__ A = (mode == 0) ? g_A0 : (mode == 1) ? g_A1 : g_A2;
    __half2* __restrict__ V = (mode == 0) ? g_Vx : (mode == 1) ? g_Vy : g_Vz;

#pragma unroll
    for (int j = 0; j < 16; ++j) {
        int e = t + 256 * j;
        int cl = e & 15, u = e >> 4;
        sh[cl][u] = __half22float2(A[(u * 256 + v) * 128 + c0 + cl]);
    }
    __syncthreads();
    fft256_16lines(sh, t >> 4, t & 15);

#pragma unroll
    for (int j = 0; j < 16; ++j) {
        int e = t + 256 * j;
        int cl = e & 15, u = e >> 4;
        float2 val = sh[cl][u];
        V[(u * 256 + v) * 128 + c0 + cl] = __floats2half2_rn(val.x, val.y);
    }
}

// ----------------------------------------------------------------------------
// Sampling: one warp per point, lane = 4 channels. All 12 tap loads issued
// up front (max MLP), then the arithmetic.
// ----------------------------------------------------------------------------
__device__ __forceinline__ int corner_base(float gu, float gv, int& u1d, int& v1d,
                                           float& wu, float& wv) {
    float iu = (gu + 1.f) * 127.5f;
    float iv = (gv + 1.f) * 127.5f;
    float u0f = floorf(iu), v0f = floorf(iv);
    wu = iu - u0f; wv = iv - v0f;
    int u0 = (int)u0f; u0 = max(0, min(u0, 255)); int u1 = min(u0 + 1, 255);
    int v0 = (int)v0f; v0 = max(0, min(v0, 255)); int v1 = min(v0 + 1, 255);
    u1d = (u1 - u0) * 256 * 128;
    v1d = (v1 - v0) * 128;
    return (u0 * 256 + v0) * 128;
}

__device__ __forceinline__ float plane_reduce(const uint4 q[4],
                                              float wu, float wv, float bang, int d0) {
    float w00 = (1.f - wu) * (1.f - wv), w01 = (1.f - wu) * wv;
    float w10 = wu * (1.f - wv),         w11 = wu * wv;
    float res = 0.f;
    const unsigned* q00 = (const unsigned*)&q[0];
    const unsigned* q01 = (const unsigned*)&q[1];
    const unsigned* q10 = (const unsigned*)&q[2];
    const unsigned* q11 = (const unsigned*)&q[3];
#pragma unroll
    for (int j = 0; j < 4; ++j) {
        float2 a = __half22float2(*(const __half2*)&q00[j]);
        float2 b = __half22float2(*(const __half2*)&q01[j]);
        float2 c = __half22float2(*(const __half2*)&q10[j]);
        float2 d = __half22float2(*(const __half2*)&q11[j]);
        float sr = w00 * a.x + w01 * b.x + w10 * c.x + w11 * d.x;
        float si = w00 * a.y + w01 * b.y + w10 * c.y + w11 * d.y;
        int dd = d0 + j;
        float sn, cn;
        __sincosf(bang * (float)dd, &sn, &cn);
        float sc = (dd > 0) ? 2.f : 1.f;
        res += sc * (sr * cn - si * sn);
    }
    return res;
}

__global__ __launch_bounds__(256) void k_sample(const float* __restrict__ pts,
                                                float* __restrict__ out) {
    int gw = (blockIdx.x * 256 + threadIdx.x) >> 5;
    int lane = threadIdx.x & 31;
    if (gw >= 131072) return;
    float xs = pts[gw * 3 + 0];
    float ys = pts[gw * 3 + 1];
    float zs = pts[gw * 3 + 2];
    int cbase = lane * 4;
    int d0 = cbase & 7;

    // plane X: (u=ys, v=zs) twiddle xs | plane Y: (u=xs, v=zs) twiddle ys
    // plane Z: (u=xs, v=ys) twiddle zs
    float wuX, wvX, wuY, wvY, wuZ, wvZ;
    int u1X, v1X, u1Y, v1Y, u1Z, v1Z;
    int bX = corner_base(ys, zs, u1X, v1X, wuX, wvX) + cbase;
    int bY = corner_base(xs, zs, u1Y, v1Y, wuY, wvY) + cbase;
    int bZ = corner_base(xs, ys, u1Z, v1Z, wuZ, wvZ) + cbase;

    uint4 qX[4], qY[4], qZ[4];
    qX[0] = *(const uint4*)(g_Vx + bX);
    qX[1] = *(const uint4*)(g_Vx + bX + v1X);
    qX[2] = *(const uint4*)(g_Vx + bX + u1X);
    qX[3] = *(const uint4*)(g_Vx + bX + u1X + v1X);
    qY[0] = *(const uint4*)(g_Vy + bY);
    qY[1] = *(const uint4*)(g_Vy + bY + v1Y);
    qY[2] = *(const uint4*)(g_Vy + bY + u1Y);
    qY[3] = *(const uint4*)(g_Vy + bY + u1Y + v1Y);
    qZ[0] = *(const uint4*)(g_Vz + bZ);
    qZ[1] = *(const uint4*)(g_Vz + bZ + v1Z);
    qZ[2] = *(const uint4*)(g_Vz + bZ + u1Z);
    qZ[3] = *(const uint4*)(g_Vz + bZ + u1Z + v1Z);

    const float K = TWO_PI * 0.5f * (255.f / 256.f);
    float acc = plane_reduce(qX, wuX, wvX, (xs + 1.f) * K, d0)
              + plane_reduce(qY, wuY, wvY, (ys + 1.f) * K, d0)
              + plane_reduce(qZ, wuZ, wvZ, (zs + 1.f) * K, d0);

    acc += __shfl_xor_sync(0xffffffffu, acc, 1);
    float vv = __shfl_sync(0xffffffffu, acc, (lane & 15) * 2);
    if (lane < 16) out[gw * 16 + lane] = vv;
}

extern "C" void kernel_launch(void* const* d_in, const int* in_sizes, int n_in,
                              void* d_out, int out_size) {
    const float* pts    = (const float*)d_in[0];
    const float* Fx_re  = (const float*)d_in[1];
    const float* Fx_im  = (const float*)d_in[2];
    const float* Fy_re  = (const float*)d_in[3];
    const float* Fy_im  = (const float*)d_in[4];
    const float* Fz_re  = (const float*)d_in[5];
    const float* Fz_im  = (const float*)d_in[6];
    const float* alphap = (const float*)d_in[7];
    float* out = (float*)d_out;

    k_fft_pass1_all<<<6144, 256>>>(Fx_re, Fx_im, Fy_re, Fy_im, Fz_re, Fz_im, alphap);
    k_fft_pass2_all<<<6144, 256>>>();
    k_sample<<<131072 * 32 / 256, 256>>>(pts, out);
}

// round 7
// speedup vs baseline: 3.4186x; 1.0206x over previous
#include <cuda_runtime.h>
#include <cuda_fp16.h>
#include <math.h>

#define TWO_PI 6.283185307179586f

// ---- static device scratch (allocation-free) ----
// FFT intermediates (after v-axis transform), channel-last fp16: A[u][v][c]
__device__ __align__(16) __half2 g_A0[256 * 256 * 128];  // 33.5 MB each
__device__ __align__(16) __half2 g_A1[256 * 256 * 128];
__device__ __align__(16) __half2 g_A2[256 * 256 * 128];
// Sampled volumes, channel-last fp16: V[u][v][c]
__device__ __align__(16) __half2 g_Vx[256 * 256 * 128];
__device__ __align__(16) __half2 g_Vy[256 * 256 * 128];
__device__ __align__(16) __half2 g_Vz[256 * 256 * 128];

#define SH_R 273   // smem row stride (float2 units)

// ---------------------------------------------------------------------------
// complex helpers
// ---------------------------------------------------------------------------
__device__ __forceinline__ float2 cmul(float2 a, float2 b) {
    return make_float2(fmaf(a.x, b.x, -a.y * b.y), fmaf(a.x, b.y, a.y * b.x));
}
__device__ __forceinline__ float2 cmul_imm(float2 a, float c, float s) {
    return make_float2(fmaf(a.x, c, a.y * (-s)), fmaf(a.y, c, a.x * s));
}
__device__ __forceinline__ float2 cadd(float2 a, float2 b) { return make_float2(a.x + b.x, a.y + b.y); }
__device__ __forceinline__ float2 csub(float2 a, float2 b) { return make_float2(a.x - b.x, a.y - b.y); }
__device__ __forceinline__ float2 muli(float2 a) { return make_float2(-a.y, a.x); }

__device__ __forceinline__ void dft4(float2 x0, float2 x1, float2 x2, float2 x3,
                                     float2& X0, float2& X1, float2& X2, float2& X3) {
    float2 t0 = cadd(x0, x2), t1 = csub(x0, x2);
    float2 t2 = cadd(x1, x3), t3 = csub(x1, x3);
    X0 = cadd(t0, t2);
    X2 = csub(t0, t2);
    float2 it3 = muli(t3);
    X1 = cadd(t1, it3);
    X3 = csub(t1, it3);
}

// inverse 16-point DFT, radix-4x4, natural-order in/out.
__device__ __forceinline__ void ifft16(const float2 x[16], float2 X[16]) {
    const float C  = 0.70710678118654752f;
    const float c1 = 0.92387953251128676f;
    const float s1 = 0.38268343236508977f;
    float2 y[16];
#pragma unroll
    for (int k1 = 0; k1 < 4; ++k1)
        dft4(x[k1], x[k1 + 4], x[k1 + 8], x[k1 + 12],
             y[4 * k1 + 0], y[4 * k1 + 1], y[4 * k1 + 2], y[4 * k1 + 3]);
    y[4 * 1 + 1] = cmul_imm(y[4 * 1 + 1],  c1,  s1);
    y[4 * 1 + 2] = cmul_imm(y[4 * 1 + 2],   C,   C);
    y[4 * 1 + 3] = cmul_imm(y[4 * 1 + 3],  s1,  c1);
    y[4 * 2 + 1] = cmul_imm(y[4 * 2 + 1],   C,   C);
    y[4 * 2 + 2] = muli(y[4 * 2 + 2]);
    y[4 * 2 + 3] = cmul_imm(y[4 * 2 + 3],  -C,   C);
    y[4 * 3 + 1] = cmul_imm(y[4 * 3 + 1],  s1,  c1);
    y[4 * 3 + 2] = cmul_imm(y[4 * 3 + 2],  -C,   C);
    y[4 * 3 + 3] = cmul_imm(y[4 * 3 + 3], -c1, -s1);
#pragma unroll
    for (int n2 = 0; n2 < 4; ++n2) {
        float2 z0, z1, z2, z3;
        dft4(y[4 * 0 + n2], y[4 * 1 + n2], y[4 * 2 + n2], y[4 * 3 + n2], z0, z1, z2, z3);
        X[n2] = z0; X[4 + n2] = z1; X[8 + n2] = z2; X[12 + n2] = z3;
    }
}

// 256-point inverse DFT core: stage-1 input x[k1] already in registers.
// On exit sh[line][v] holds the transformed line (v = output index).
__device__ __forceinline__ void fft256_core(const float2 x[16], float2 (*sh)[SH_R],
                                            int line, int k0) {
    float2 X[16];
    ifft16(x, X);
    float sb, cb;
    __sincosf((float)k0 * (TWO_PI / 256.f), &sb, &cb);
    float2 base = make_float2(cb, sb);
    float2 tw = make_float2(1.f, 0.f);
#pragma unroll
    for (int n0 = 0; n0 < 16; ++n0) {
        sh[line][k0 * 17 + n0] = cmul(X[n0], tw);
        tw = cmul(tw, base);
    }
    __syncthreads();
    const int n0 = k0;
    float2 y[16];
#pragma unroll
    for (int kk = 0; kk < 16; ++kk) y[kk] = sh[line][kk * 17 + n0];
    __syncthreads();
    float2 Y[16];
    ifft16(y, Y);
#pragma unroll
    for (int n1 = 0; n1 < 16; ++n1) sh[line][n1 * 16 + n0] = Y[n1];
    __syncthreads();
}

// ----------------------------------------------------------------------------
// Pass 1 (all 3 volumes): inverse DFT along contiguous axis v.
// blockIdx: mode = b>>11; within mode: u = b&255, c0 = ((b>>8)&7)*16.
// Modes 0/1: stage-1 inputs read DIRECTLY from global (coalesced 64B runs).
// Mode 2 (d-interleaved): staged via smem as before.
// Writes channel-last fp16 A[u][v][c].
// ----------------------------------------------------------------------------
__global__ __launch_bounds__(256) void k_fft_pass1_all(
        const float* __restrict__ x_re, const float* __restrict__ x_im,
        const float* __restrict__ y_re, const float* __restrict__ y_im,
        const float* __restrict__ z_re, const float* __restrict__ z_im,
        const float* __restrict__ alphap) {
    __shared__ float2 sh[16][SH_R];
    const int t = threadIdx.x;
    const int line = t >> 4, k0 = t & 15;

    const float ap = alphap[0];
    const float bxx = 10.f * ap;
    const float alpha = (bxx > 1.f) ? ap : 0.1f * log1pf(expf(fminf(bxx, 30.f)));

    const int bb = blockIdx.x;
    const int mode = bb >> 11;
    const int b = bb & 2047;
    const int u = b & 255;
    const int c0 = (b >> 8) * 16;

    float2 x[16];
    if (mode == 2) {
        const int f0 = c0 >> 3;
        const int base = f0 * 524288 + u * 2048;
#pragma unroll
        for (int j = 0; j < 16; ++j) {
            int e = t + 256 * j;                  // 0..4095
            int f_loc = e >> 11, r = e & 2047;
            int d = r & 7, v = r >> 3;
            sh[f_loc * 8 + d][v] = make_float2(z_re[base + f_loc * 524288 + r] * alpha,
                                               z_im[base + f_loc * 524288 + r] * alpha);
        }
        __syncthreads();
#pragma unroll
        for (int k1 = 0; k1 < 16; ++k1) x[k1] = sh[line][k1 * 16 + k0];
        __syncthreads();
    } else {
        const float* __restrict__ re = (mode == 0) ? x_re : y_re;
        const float* __restrict__ im = (mode == 0) ? x_im : y_im;
        int c = c0 + line;
        int base;
        if (mode == 0) base = c * 65536 + u * 256;
        else           base = (c >> 3) * 524288 + u * 2048 + (c & 7) * 256;
#pragma unroll
        for (int k1 = 0; k1 < 16; ++k1) {
            int idx = base + k1 * 16 + k0;
            x[k1] = make_float2(re[idx] * alpha, im[idx] * alpha);
        }
    }
    fft256_core(x, sh, line, k0);

    __half2* __restrict__ A = (mode == 0) ? g_A0 : (mode == 1) ? g_A1 : g_A2;
#pragma unroll
    for (int j = 0; j < 16; ++j) {
        int e = t + 256 * j;
        int cl = e & 15, v = e >> 4;
        float2 val = sh[cl][v];
        A[(u * 256 + v) * 128 + c0 + cl] = __floats2half2_rn(val.x, val.y);
    }
}

// ----------------------------------------------------------------------------
// Pass 2 (all 3 volumes): inverse DFT along u. Block = 16 channels at one v.
// ----------------------------------------------------------------------------
__global__ __launch_bounds__(256) void k_fft_pass2_all() {
    __shared__ float2 sh[16][SH_R];
    const int t = threadIdx.x;
    const int line = t >> 4, k0 = t & 15;

    const int bb = blockIdx.x;
    const int mode = bb >> 11;
    const int b = bb & 2047;
    const int v = b & 255;
    const int c0 = (b >> 8) * 16;

    const __half2* __restrict__ A = (mode == 0) ? g_A0 : (mode == 1) ? g_A1 : g_A2;
    __half2* __restrict__ V = (mode == 0) ? g_Vx : (mode == 1) ? g_Vy : g_Vz;

#pragma unroll
    for (int j = 0; j < 16; ++j) {
        int e = t + 256 * j;
        int cl = e & 15, u = e >> 4;
        sh[cl][u] = __half22float2(A[(u * 256 + v) * 128 + c0 + cl]);
    }
    __syncthreads();
    float2 x[16];
#pragma unroll
    for (int k1 = 0; k1 < 16; ++k1) x[k1] = sh[line][k1 * 16 + k0];
    __syncthreads();
    fft256_core(x, sh, line, k0);

#pragma unroll
    for (int j = 0; j < 16; ++j) {
        int e = t + 256 * j;
        int cl = e & 15, u = e >> 4;
        float2 val = sh[cl][u];
        V[(u * 256 + v) * 128 + c0 + cl] = __floats2half2_rn(val.x, val.y);
    }
}

// ----------------------------------------------------------------------------
// Sampling: one warp per point, lane = 4 channels. All 12 tap loads issued
// up front; twiddles via 1 sincos + exponential recurrence per plane.
// ----------------------------------------------------------------------------
__device__ __forceinline__ int corner_base(float gu, float gv, int& u1d, int& v1d,
                                           float& wu, float& wv) {
    float iu = (gu + 1.f) * 127.5f;
    float iv = (gv + 1.f) * 127.5f;
    float u0f = floorf(iu), v0f = floorf(iv);
    wu = iu - u0f; wv = iv - v0f;
    int u0 = (int)u0f; u0 = max(0, min(u0, 255)); int u1 = min(u0 + 1, 255);
    int v0 = (int)v0f; v0 = max(0, min(v0, 255)); int v1 = min(v0 + 1, 255);
    u1d = (u1 - u0) * 256 * 128;
    v1d = (v1 - v0) * 128;
    return (u0 * 256 + v0) * 128;
}

__device__ __forceinline__ float plane_reduce(const uint4 q[4],
                                              float wu, float wv, float bang, int d0) {
    float w00 = (1.f - wu) * (1.f - wv), w01 = (1.f - wu) * wv;
    float w10 = wu * (1.f - wv),         w11 = wu * wv;
    // e^{i bang d} for d = d0..d0+3, d0 in {0,4}: 1 sincos + chain
    float sn1, cn1;
    __sincosf(bang, &sn1, &cn1);
    float2 w1 = make_float2(cn1, sn1);
    float2 w2 = cmul(w1, w1);
    float2 w4 = cmul(w2, w2);
    float2 cur = (d0 == 0) ? make_float2(1.f, 0.f) : w4;
    float res = 0.f;
    const unsigned* q00 = (const unsigned*)&q[0];
    const unsigned* q01 = (const unsigned*)&q[1];
    const unsigned* q10 = (const unsigned*)&q[2];
    const unsigned* q11 = (const unsigned*)&q[3];
#pragma unroll
    for (int j = 0; j < 4; ++j) {
        float2 a = __half22float2(*(const __half2*)&q00[j]);
        float2 b = __half22float2(*(const __half2*)&q01[j]);
        float2 c = __half22float2(*(const __half2*)&q10[j]);
        float2 d = __half22float2(*(const __half2*)&q11[j]);
        float sr = w00 * a.x + w01 * b.x + w10 * c.x + w11 * d.x;
        float si = w00 * a.y + w01 * b.y + w10 * c.y + w11 * d.y;
        float sc = (d0 + j > 0) ? 2.f : 1.f;
        res += sc * (sr * cur.x - si * cur.y);
        cur = cmul(cur, w1);
    }
    return res;
}

__global__ __launch_bounds__(256) void k_sample(const float* __restrict__ pts,
                                                float* __restrict__ out) {
    int gw = (blockIdx.x * 256 + threadIdx.x) >> 5;
    int lane = threadIdx.x & 31;
    if (gw >= 131072) return;
    float xs = pts[gw * 3 + 0];
    float ys = pts[gw * 3 + 1];
    float zs = pts[gw * 3 + 2];
    int cbase = lane * 4;
    int d0 = cbase & 7;

    float wuX, wvX, wuY, wvY, wuZ, wvZ;
    int u1X, v1X, u1Y, v1Y, u1Z, v1Z;
    int bX = corner_base(ys, zs, u1X, v1X, wuX, wvX) + cbase;
    int bY = corner_base(xs, zs, u1Y, v1Y, wuY, wvY) + cbase;
    int bZ = corner_base(xs, ys, u1Z, v1Z, wuZ, wvZ) + cbase;

    uint4 qX[4], qY[4], qZ[4];
    qX[0] = *(const uint4*)(g_Vx + bX);
    qX[1] = *(const uint4*)(g_Vx + bX + v1X);
    qX[2] = *(const uint4*)(g_Vx + bX + u1X);
    qX[3] = *(const uint4*)(g_Vx + bX + u1X + v1X);
    qY[0] = *(const uint4*)(g_Vy + bY);
    qY[1] = *(const uint4*)(g_Vy + bY + v1Y);
    qY[2] = *(const uint4*)(g_Vy + bY + u1Y);
    qY[3] = *(const uint4*)(g_Vy + bY + u1Y + v1Y);
    qZ[0] = *(const uint4*)(g_Vz + bZ);
    qZ[1] = *(const uint4*)(g_Vz + bZ + v1Z);
    qZ[2] = *(const uint4*)(g_Vz + bZ + u1Z);
    qZ[3] = *(const uint4*)(g_Vz + bZ + u1Z + v1Z);

    const float K = TWO_PI * 0.5f * (255.f / 256.f);
    float acc = plane_reduce(qX, wuX, wvX, (xs + 1.f) * K, d0)
              + plane_reduce(qY, wuY, wvY, (ys + 1.f) * K, d0)
              + plane_reduce(qZ, wuZ, wvZ, (zs + 1.f) * K, d0);

    acc += __shfl_xor_sync(0xffffffffu, acc, 1);
    float vv = __shfl_sync(0xffffffffu, acc, (lane & 15) * 2);
    if (lane < 16) out[gw * 16 + lane] = vv;
}

extern "C" void kernel_launch(void* const* d_in, const int* in_sizes, int n_in,
                              void* d_out, int out_size) {
    const float* pts    = (const float*)d_in[0];
    const float* Fx_re  = (const float*)d_in[1];
    const float* Fx_im  = (const float*)d_in[2];
    const float* Fy_re  = (const float*)d_in[3];
    const float* Fy_im  = (const float*)d_in[4];
    const float* Fz_re  = (const float*)d_in[5];
    const float* Fz_im  = (const float*)d_in[6];
    const float* alphap = (const float*)d_in[7];
    float* out = (float*)d_out;

    k_fft_pass1_all<<<6144, 256>>>(Fx_re, Fx_im, Fy_re, Fy_im, Fz_re, Fz_im, alphap);
    k_fft_pass2_all<<<6144, 256>>>();
    k_sample<<<131072 * 32 / 256, 256>>>(pts, out);
}